// round 2
// baseline (speedup 1.0000x reference)
#include <cuda_runtime.h>
#include <cuda_bf16.h>
#include <math.h>

// Problem constants
#define B_  2
#define C_  192       // DINNER
#define Hh  48
#define Ww  48
#define L_  2304      // H*W
#define K_  4
#define N_  16
#define R_  12
#define D44 44        // R + 2N
#define KC  (K_*C_)   // 768

// ---------------- scratch (device globals; no allocation allowed) ------------
__device__ float g_xT[B_ * C_ * L_];              // transposed x (stream-1 activations)
__device__ float g_Q [B_ * K_ * D44 * L_];        // x_dbl in stream order
__device__ float g_BC[B_ * K_ * L_ * 32];         // B,C repacked: [b][k][p][32] (B:0..15, C:16..31)
__device__ float g_SP[B_ * K_ * C_ * L_];         // softplus(delta + bias), stream order
__device__ float g_Y [B_ * K_ * C_ * L_];         // scan output, stream order

// ---------------- kernel 1: transpose x -> xT (stream 1 activations) ---------
// xT[b][c][w*H + h] = x[b][c][h*W + w]
__global__ void k_transpose(const float* __restrict__ x) {
    int bc = blockIdx.x;                 // 0..383  (b*C + c)
    const float* src = x + (size_t)bc * L_;
    float* dst = g_xT + (size_t)bc * L_;
    __shared__ float s[L_];
    for (int i = threadIdx.x; i < L_; i += blockDim.x) s[i] = src[i];
    __syncthreads();
    for (int i = threadIdx.x; i < L_; i += blockDim.x) {
        int w = i / Hh, h = i % Hh;      // dst index i = w*H + h
        dst[i] = s[h * Ww + w];
    }
}

// ---------------- kernel 2: projection GEMM -----------------------------------
// For stream s (0: x, 1: xT) compute rows for k = s and k = s+2 (88 rows of W),
// Q[b][k][d][p] = sum_c W[k][d][c] * stream_s[b][c][p]   (stream order p)
// Block: 96(row-padded) x 64 output tile, 256 threads (16x16), k-chunks of 16.
__global__ void k_proj(const float* __restrict__ x,
                       const float* __restrict__ Wp) {  // x_proj_weight [K*44][192]
    int bs = blockIdx.z;            // 0..3 : b*2 + s
    int b  = bs >> 1, s = bs & 1;
    int p0 = blockIdx.x * 64;

    const float* X = (s ? g_xT : x) + (size_t)b * C_ * L_;

    __shared__ float Ws[16][96];    // Ws[kk][m]
    __shared__ float Xs[16][64];    // Xs[kk][pp]

    int tid = threadIdx.x;
    int tx = tid & 15;              // col group
    int ty = tid >> 4;              // row group

    float acc[6][4];
#pragma unroll
    for (int i = 0; i < 6; i++)
#pragma unroll
        for (int j = 0; j < 4; j++) acc[i][j] = 0.f;

    for (int c0 = 0; c0 < C_; c0 += 16) {
        // load weights tile: 96 x 16
        for (int idx = tid; idx < 96 * 16; idx += 256) {
            int m = idx >> 4, kk = idx & 15;
            float v = 0.f;
            if (m < 88) {
                int k = s + (m < D44 ? 0 : 2);
                int d = (m < D44) ? m : (m - D44);
                v = Wp[(size_t)(k * D44 + d) * C_ + c0 + kk];
            }
            Ws[kk][m] = v;
        }
        // load activation tile: 16 x 64
        for (int idx = tid; idx < 16 * 64; idx += 256) {
            int c = idx >> 6, pp = idx & 63;
            Xs[c][pp] = X[(size_t)(c0 + c) * L_ + p0 + pp];
        }
        __syncthreads();
#pragma unroll
        for (int kk = 0; kk < 16; kk++) {
            float xa[4], wa[6];
#pragma unroll
            for (int j = 0; j < 4; j++) xa[j] = Xs[kk][tx + 16 * j];
#pragma unroll
            for (int i = 0; i < 6; i++) wa[i] = Ws[kk][ty + 16 * i];
#pragma unroll
            for (int i = 0; i < 6; i++)
#pragma unroll
                for (int j = 0; j < 4; j++) acc[i][j] = fmaf(wa[i], xa[j], acc[i][j]);
        }
        __syncthreads();
    }

#pragma unroll
    for (int i = 0; i < 6; i++) {
        int m = ty + 16 * i;
        if (m < 88) {
            int k = s + (m < D44 ? 0 : 2);
            int d = (m < D44) ? m : (m - D44);
            float* qrow = g_Q + (size_t)((b * K_ + k) * D44 + d) * L_ + p0;
#pragma unroll
            for (int j = 0; j < 4; j++) qrow[tx + 16 * j] = acc[i][j];
        }
    }
}

// ---------------- kernel 3: dt projection + softplus --------------------------
// SP[b][k][c][p] = softplus( sum_r dtw[k][c][r] * Q[b][k][r][p] + dt_bias[k*C+c] )
__global__ void k_dtsp(const float* __restrict__ dtw,      // [K][C][R]
                       const float* __restrict__ dt_bias)  // [K*C]
{
    int b = blockIdx.z, k = blockIdx.y;
    int p0 = blockIdx.x * 128;
    __shared__ float dts[R_][128];
    __shared__ float wsm[C_ * R_];

    int tid = threadIdx.x;
    for (int idx = tid; idx < R_ * 128; idx += 256) {
        int r = idx >> 7, pp = idx & 127;
        dts[r][pp] = g_Q[(size_t)((b * K_ + k) * D44 + r) * L_ + p0 + pp];
    }
    for (int idx = tid; idx < C_ * R_; idx += 256)
        wsm[idx] = dtw[(size_t)k * C_ * R_ + idx];
    __syncthreads();

    int pp = tid & 127;
    for (int c = (tid >> 7); c < C_; c += 2) {
        float accv = dt_bias[k * C_ + c];
#pragma unroll
        for (int r = 0; r < R_; r++) accv = fmaf(wsm[c * R_ + r], dts[r][pp], accv);
        float sp = (accv > 20.f) ? accv : log1pf(__expf(accv));
        g_SP[(size_t)((b * K_ + k) * C_ + c) * L_ + p0 + pp] = sp;
    }
}

// ---------------- kernel 4: repack B,C rows into [p][32] ----------------------
__global__ void k_repack() {
    int b = blockIdx.z, k = blockIdx.y;
    int p0 = blockIdx.x * 128;
    __shared__ float s[32][129];
    int tid = threadIdx.x;
    for (int idx = tid; idx < 32 * 128; idx += 256) {
        int j = idx >> 7, pp = idx & 127;
        s[j][pp] = g_Q[(size_t)((b * K_ + k) * D44 + 12 + j) * L_ + p0 + pp];
    }
    __syncthreads();
    int j = tid & 31;
    float* dst = g_BC + ((size_t)(b * K_ + k) * L_ + p0) * 32;
    for (int pp = tid >> 5; pp < 128; pp += 8)
        dst[pp * 32 + j] = s[j][pp];
}

// ---------------- kernel 5: selective scan ------------------------------------
// Warp = 2 adjacent channels (same b,k); 16 lanes per channel, one state n each.
__global__ void k_scan(const float* __restrict__ x,
                       const float* __restrict__ A_logs,   // [KC][N]
                       const float* __restrict__ Ds)       // [KC]
{
    int warpId = threadIdx.x >> 5;
    int lane = threadIdx.x & 31;
    int gw = blockIdx.x * 4 + warpId;       // 0..767
    int half = lane >> 4, n = lane & 15;
    int ch = gw * 2 + half;                 // 0..1535  == (b*K + k)*C + c
    int c = ch % C_;
    int k = (ch / C_) & 3;
    int b = ch / (K_ * C_);
    int kc = k * C_ + c;

    float a  = -__expf(A_logs[kc * N_ + n]);
    float Dv = Ds[kc];

    const float* sp = g_SP + (size_t)ch * L_;
    const float* u  = ((k & 1) ? g_xT : x) + (size_t)(b * C_ + c) * L_;
    const float* bc = g_BC + (size_t)(b * K_ + k) * L_ * 32;
    float* y        = g_Y + (size_t)ch * L_;

    bool fwd = (k < 2);
    float h = 0.f;

    for (int t = 0; t < L_ / 4; t++) {
        int q = fwd ? (4 * t) : (L_ - 4 - 4 * t);
        float4 s4 = *reinterpret_cast<const float4*>(sp + q);
        float4 u4 = *reinterpret_cast<const float4*>(u + q);
        float se[4] = {s4.x, s4.y, s4.z, s4.w};
        float ue[4] = {u4.x, u4.y, u4.z, u4.w};
        float yv[4];
#pragma unroll
        for (int j = 0; j < 4; j++) {
            int e = fwd ? j : (3 - j);
            float spv = se[e], uv = ue[e];
            int p = q + e;
            float Bn = bc[p * 32 + n];
            float Cn = bc[p * 32 + 16 + n];
            float dA = __expf(spv * a);
            h = fmaf(dA, h, spv * uv * Bn);
            float yp = h * Cn;
            yp += __shfl_xor_sync(0xffffffffu, yp, 8);
            yp += __shfl_xor_sync(0xffffffffu, yp, 4);
            yp += __shfl_xor_sync(0xffffffffu, yp, 2);
            yp += __shfl_xor_sync(0xffffffffu, yp, 1);
            yv[e] = fmaf(Dv, uv, yp);
        }
        if (n == 0)
            *reinterpret_cast<float4*>(y + q) = make_float4(yv[0], yv[1], yv[2], yv[3]);
    }
}

// ---------------- kernel 6: cross merge ---------------------------------------
// out[b][c][h*W+w] = Y[b,0,c,hw] + Y[b,2,c,hw] + Y[b,1,c,w*H+h] + Y[b,3,c,w*H+h]
__global__ void k_merge(float* __restrict__ out) {
    int bc = blockIdx.x;           // b*C + c
    int b = bc / C_, c = bc % C_;
    const float* y0 = g_Y + (size_t)((b * K_ + 0) * C_ + c) * L_;
    const float* y1 = g_Y + (size_t)((b * K_ + 1) * C_ + c) * L_;
    const float* y2 = g_Y + (size_t)((b * K_ + 2) * C_ + c) * L_;
    const float* y3 = g_Y + (size_t)((b * K_ + 3) * C_ + c) * L_;
    __shared__ float s1[L_];
    for (int i = threadIdx.x; i < L_; i += blockDim.x)
        s1[i] = y1[i] + y3[i];
    __syncthreads();
    float* o = out + (size_t)bc * L_;
    for (int i = threadIdx.x; i < L_; i += blockDim.x) {
        int h = i / Ww, w = i % Ww;
        o[i] = y0[i] + y2[i] + s1[w * Hh + h];
    }
}

// ---------------- launch -------------------------------------------------------
extern "C" void kernel_launch(void* const* d_in, const int* in_sizes, int n_in,
                              void* d_out, int out_size) {
    const float* x       = (const float*)d_in[0];  // [B,C,H,W]
    const float* xpw     = (const float*)d_in[1];  // [K,44,C]
    const float* dtw     = (const float*)d_in[2];  // [K,C,R]
    const float* A_logs  = (const float*)d_in[3];  // [KC,N]
    const float* Ds      = (const float*)d_in[4];  // [KC]
    const float* dt_bias = (const float*)d_in[5];  // [KC]
    float* out = (float*)d_out;

    k_transpose<<<B_ * C_, 256>>>(x);

    {
        dim3 grid(L_ / 64, 1, 4);
        k_proj<<<grid, 256>>>(x, xpw);
    }
    {
        dim3 grid(L_ / 128, K_, B_);
        k_dtsp<<<grid, 256>>>(dtw, dt_bias);
        k_repack<<<grid, 256>>>();
    }
    k_scan<<<192, 128>>>(x, A_logs, Ds);
    k_merge<<<B_ * C_, 256>>>(out);
}

// round 3
// speedup vs baseline: 3.6804x; 3.6804x over previous
#include <cuda_runtime.h>
#include <cuda_bf16.h>
#include <math.h>

// Problem constants
#define B_  2
#define C_  192       // DINNER
#define Hh  48
#define Ww  48
#define L_  2304      // H*W
#define K_  4
#define N_  16
#define R_  12
#define D44 44        // R + 2N
#define KC  (K_*C_)   // 768

// ---------------- scratch (device globals; no allocation allowed) ------------
__device__ float g_xT[B_ * C_ * L_];              // transposed x (stream-1 activations)
__device__ float g_Q [B_ * K_ * D44 * L_];        // x_dbl in stream order
__device__ float g_BC[B_ * K_ * L_ * 32];         // B,C interleaved: [b][k][p][n][{B,C}]
__device__ float g_SP[B_ * K_ * C_ * L_];         // softplus(delta + bias), stream order
__device__ float g_Y [B_ * K_ * C_ * L_];         // scan output, stream order

// ---------------- kernel 1: transpose x -> xT (stream 1 activations) ---------
__global__ void k_transpose(const float* __restrict__ x) {
    int bc = blockIdx.x;                 // 0..383  (b*C + c)
    const float* src = x + (size_t)bc * L_;
    float* dst = g_xT + (size_t)bc * L_;
    __shared__ float s[L_];
    for (int i = threadIdx.x; i < L_; i += blockDim.x) s[i] = src[i];
    __syncthreads();
    for (int i = threadIdx.x; i < L_; i += blockDim.x) {
        int w = i / Hh, h = i % Hh;      // dst index i = w*H + h
        dst[i] = s[h * Ww + w];
    }
}

// ---------------- kernel 2: projection GEMM -----------------------------------
__global__ void k_proj(const float* __restrict__ x,
                       const float* __restrict__ Wp) {  // x_proj_weight [K*44][192]
    int bs = blockIdx.z;            // 0..3 : b*2 + s
    int b  = bs >> 1, s = bs & 1;
    int p0 = blockIdx.x * 64;

    const float* X = (s ? g_xT : x) + (size_t)b * C_ * L_;

    __shared__ float Ws[16][96];    // Ws[kk][m]
    __shared__ float Xs[16][64];    // Xs[kk][pp]

    int tid = threadIdx.x;
    int tx = tid & 15;              // col group
    int ty = tid >> 4;              // row group

    float acc[6][4];
#pragma unroll
    for (int i = 0; i < 6; i++)
#pragma unroll
        for (int j = 0; j < 4; j++) acc[i][j] = 0.f;

    for (int c0 = 0; c0 < C_; c0 += 16) {
        for (int idx = tid; idx < 96 * 16; idx += 256) {
            int m = idx >> 4, kk = idx & 15;
            float v = 0.f;
            if (m < 88) {
                int k = s + (m < D44 ? 0 : 2);
                int d = (m < D44) ? m : (m - D44);
                v = Wp[(size_t)(k * D44 + d) * C_ + c0 + kk];
            }
            Ws[kk][m] = v;
        }
        for (int idx = tid; idx < 16 * 64; idx += 256) {
            int c = idx >> 6, pp = idx & 63;
            Xs[c][pp] = X[(size_t)(c0 + c) * L_ + p0 + pp];
        }
        __syncthreads();
#pragma unroll
        for (int kk = 0; kk < 16; kk++) {
            float xa[4], wa[6];
#pragma unroll
            for (int j = 0; j < 4; j++) xa[j] = Xs[kk][tx + 16 * j];
#pragma unroll
            for (int i = 0; i < 6; i++) wa[i] = Ws[kk][ty + 16 * i];
#pragma unroll
            for (int i = 0; i < 6; i++)
#pragma unroll
                for (int j = 0; j < 4; j++) acc[i][j] = fmaf(wa[i], xa[j], acc[i][j]);
        }
        __syncthreads();
    }

#pragma unroll
    for (int i = 0; i < 6; i++) {
        int m = ty + 16 * i;
        if (m < 88) {
            int k = s + (m < D44 ? 0 : 2);
            int d = (m < D44) ? m : (m - D44);
            float* qrow = g_Q + (size_t)((b * K_ + k) * D44 + d) * L_ + p0;
#pragma unroll
            for (int j = 0; j < 4; j++) qrow[tx + 16 * j] = acc[i][j];
        }
    }
}

// ---------------- kernel 3: dt projection + softplus --------------------------
__global__ void k_dtsp(const float* __restrict__ dtw,      // [K][C][R]
                       const float* __restrict__ dt_bias)  // [K*C]
{
    int b = blockIdx.z, k = blockIdx.y;
    int p0 = blockIdx.x * 128;
    __shared__ float dts[R_][128];
    __shared__ float wsm[C_ * R_];

    int tid = threadIdx.x;
    for (int idx = tid; idx < R_ * 128; idx += 256) {
        int r = idx >> 7, pp = idx & 127;
        dts[r][pp] = g_Q[(size_t)((b * K_ + k) * D44 + r) * L_ + p0 + pp];
    }
    for (int idx = tid; idx < C_ * R_; idx += 256)
        wsm[idx] = dtw[(size_t)k * C_ * R_ + idx];
    __syncthreads();

    int pp = tid & 127;
    for (int c = (tid >> 7); c < C_; c += 2) {
        float accv = dt_bias[k * C_ + c];
#pragma unroll
        for (int r = 0; r < R_; r++) accv = fmaf(wsm[c * R_ + r], dts[r][pp], accv);
        float sp = (accv > 20.f) ? accv : log1pf(__expf(accv));
        g_SP[(size_t)((b * K_ + k) * C_ + c) * L_ + p0 + pp] = sp;
    }
}

// ---------------- kernel 4: repack B,C rows, interleaved [p][n][{B,C}] --------
__global__ void k_repack() {
    int b = blockIdx.z, k = blockIdx.y;
    int p0 = blockIdx.x * 64;
    __shared__ float s[32][65];
    int tid = threadIdx.x;
    for (int idx = tid; idx < 32 * 64; idx += 256) {
        int j = idx >> 6, pp = idx & 63;
        s[j][pp] = g_Q[(size_t)((b * K_ + k) * D44 + 12 + j) * L_ + p0 + pp];
    }
    __syncthreads();
    int j = tid & 31;
    int jo = (j < 16) ? (2 * j) : (2 * (j - 16) + 1);   // interleave B/C per state
    float* dst = g_BC + ((size_t)(b * K_ + k) * L_ + p0) * 32;
    for (int pp = tid >> 5; pp < 64; pp += 8)
        dst[pp * 32 + jo] = s[j][pp];
}

// ---------------- kernel 5: selective scan (batched 16, multi-reduce) ---------
template<bool FWD>
__device__ __forceinline__ void scan_body(
    const float* __restrict__ sp, const float* __restrict__ u,
    const float* __restrict__ bc, float* __restrict__ y,
    float a, float Dv, int n)
{
    const unsigned FULL = 0xffffffffu;
    const bool hi8 = (n & 8), hi4 = (n & 4), hi2 = (n & 2), hi1 = (n & 1);
    float h = 0.f;

    for (int g = 0; g < L_ / 16; g++) {
        int q = FWD ? g * 16 : (L_ - 16 - g * 16);   // memory base of this group

        // ---- batched loads (all independent; high MLP) ----
        float spArr[16], uArr[16];
#pragma unroll
        for (int t = 0; t < 4; t++) {
            float4 s4 = *reinterpret_cast<const float4*>(sp + q + 4 * t);
            float4 u4 = *reinterpret_cast<const float4*>(u  + q + 4 * t);
            spArr[4*t+0] = s4.x; spArr[4*t+1] = s4.y; spArr[4*t+2] = s4.z; spArr[4*t+3] = s4.w;
            uArr [4*t+0] = u4.x; uArr [4*t+1] = u4.y; uArr [4*t+2] = u4.z; uArr [4*t+3] = u4.w;
        }
        float Bv[16], Cv[16];
#pragma unroll
        for (int j = 0; j < 16; j++) {
            int mj = FWD ? j : 15 - j;               // memory offset for scan step j
            float2 bcv = __ldg(reinterpret_cast<const float2*>(bc + (size_t)(q + mj) * 32) + n);
            Bv[j] = bcv.x; Cv[j] = bcv.y;
        }

        // ---- exps + dBu (independent across j) ----
        float dA[16], dBu[16];
#pragma unroll
        for (int j = 0; j < 16; j++) {
            int mj = FWD ? j : 15 - j;
            float s_ = spArr[mj];
            dA[j]  = __expf(s_ * a);
            dBu[j] = s_ * uArr[mj] * Bv[j];
        }

        // ---- serial h-chain + per-state y partials ----
        float yp[16];
#pragma unroll
        for (int j = 0; j < 16; j++) {
            h = fmaf(dA[j], h, dBu[j]);
            yp[j] = h * Cv[j];
        }

        // ---- butterfly multi-reduction: 16 positions over 16 lanes, 15 shfls ----
        float w8[8];
#pragma unroll
        for (int t = 0; t < 8; t++) {
            float keepv = hi8 ? yp[t + 8] : yp[t];
            float sendv = hi8 ? yp[t] : yp[t + 8];
            w8[t] = keepv + __shfl_xor_sync(FULL, sendv, 8);
        }
        float w4[4];
#pragma unroll
        for (int t = 0; t < 4; t++) {
            float keepv = hi4 ? w8[t + 4] : w8[t];
            float sendv = hi4 ? w8[t] : w8[t + 4];
            w4[t] = keepv + __shfl_xor_sync(FULL, sendv, 4);
        }
        float w2[2];
#pragma unroll
        for (int t = 0; t < 2; t++) {
            float keepv = hi2 ? w4[t + 2] : w4[t];
            float sendv = hi2 ? w4[t] : w4[t + 2];
            w2[t] = keepv + __shfl_xor_sync(FULL, sendv, 2);
        }
        {
            float keepv = hi1 ? w2[1] : w2[0];
            float sendv = hi1 ? w2[0] : w2[1];
            float yred = keepv + __shfl_xor_sync(FULL, sendv, 1);
            // lane n now holds y for scan step n of this group
            int p = q + (FWD ? n : 15 - n);
            y[p] = fmaf(Dv, u[p], yred);             // coalesced 64B per half-warp
        }
    }
}

__global__ void k_scan(const float* __restrict__ x,
                       const float* __restrict__ A_logs,   // [KC][N]
                       const float* __restrict__ Ds)       // [KC]
{
    int warpId = threadIdx.x >> 5;
    int lane = threadIdx.x & 31;
    int gw = blockIdx.x * 4 + warpId;       // 0..767
    int half = lane >> 4, n = lane & 15;
    int ch = gw * 2 + half;                 // (b*K + k)*C + c
    int c = ch % C_;
    int k = (ch / C_) & 3;
    int b = ch / (K_ * C_);
    int kc = k * C_ + c;

    float a  = -__expf(A_logs[kc * N_ + n]);
    float Dv = Ds[kc];

    const float* sp = g_SP + (size_t)ch * L_;
    const float* u  = ((k & 1) ? g_xT : x) + (size_t)(b * C_ + c) * L_;
    const float* bc = g_BC + (size_t)(b * K_ + k) * L_ * 32;
    float* y        = g_Y + (size_t)ch * L_;

    if (k < 2) scan_body<true >(sp, u, bc, y, a, Dv, n);
    else       scan_body<false>(sp, u, bc, y, a, Dv, n);
}

// ---------------- kernel 6: cross merge ---------------------------------------
__global__ void k_merge(float* __restrict__ out) {
    int bc = blockIdx.x;           // b*C + c
    int b = bc / C_, c = bc % C_;
    const float* y0 = g_Y + (size_t)((b * K_ + 0) * C_ + c) * L_;
    const float* y1 = g_Y + (size_t)((b * K_ + 1) * C_ + c) * L_;
    const float* y2 = g_Y + (size_t)((b * K_ + 2) * C_ + c) * L_;
    const float* y3 = g_Y + (size_t)((b * K_ + 3) * C_ + c) * L_;
    __shared__ float s1[L_];
    for (int i = threadIdx.x; i < L_; i += blockDim.x)
        s1[i] = y1[i] + y3[i];
    __syncthreads();
    float* o = out + (size_t)bc * L_;
    for (int i = threadIdx.x; i < L_; i += blockDim.x) {
        int h = i / Ww, w = i % Ww;
        o[i] = y0[i] + y2[i] + s1[w * Hh + h];
    }
}

// ---------------- launch -------------------------------------------------------
extern "C" void kernel_launch(void* const* d_in, const int* in_sizes, int n_in,
                              void* d_out, int out_size) {
    const float* x       = (const float*)d_in[0];  // [B,C,H,W]
    const float* xpw     = (const float*)d_in[1];  // [K,44,C]
    const float* dtw     = (const float*)d_in[2];  // [K,C,R]
    const float* A_logs  = (const float*)d_in[3];  // [KC,N]
    const float* Ds      = (const float*)d_in[4];  // [KC]
    const float* dt_bias = (const float*)d_in[5];  // [KC]
    float* out = (float*)d_out;

    k_transpose<<<B_ * C_, 256>>>(x);

    {
        dim3 grid(L_ / 64, 1, 4);
        k_proj<<<grid, 256>>>(x, xpw);
    }
    {
        dim3 grid(L_ / 128, K_, B_);
        k_dtsp<<<grid, 256>>>(dtw, dt_bias);
    }
    {
        dim3 grid(L_ / 64, K_, B_);
        k_repack<<<grid, 256>>>();
    }
    k_scan<<<192, 128>>>(x, A_logs, Ds);
    k_merge<<<B_ * C_, 256>>>(out);
}

// round 5
// speedup vs baseline: 6.1487x; 1.6707x over previous
#include <cuda_runtime.h>
#include <cuda_bf16.h>
#include <math.h>

// Problem constants
#define B_  2
#define C_  192       // DINNER
#define Hh  48
#define Ww  48
#define L_  2304      // H*W
#define K_  4
#define N_  16
#define R_  12
#define D44 44        // R + 2N
#define KC  (K_*C_)   // 768

#define NCHUNK 16
#define CHUNK  144    // L_/NCHUNK
#define GPC    9      // groups of 16 per chunk

// ---------------- scratch (device globals; no allocation allowed) ------------
__device__ float g_xT[B_ * C_ * L_];              // transposed x (stream-1 activations)
__device__ float g_Q [B_ * K_ * D44 * L_];        // x_dbl in stream order
__device__ float g_BC[B_ * K_ * L_ * 32];         // B,C interleaved: [b][k][p][n][{B,C}]
__device__ float g_SP[B_ * K_ * C_ * L_];         // softplus(delta + bias), stream order
__device__ float g_Y [B_ * K_ * C_ * L_];         // scan output, stream order
__device__ float g_HP [KC * B_ * NCHUNK * N_];    // chunk-local h_end  [ch][s][n]
__device__ float g_PP [KC * B_ * NCHUNK * N_];    // chunk decay prod   [ch][s][n]
__device__ float g_HIN[KC * B_ * NCHUNK * N_];    // corrected h_in     [ch][s][n]

// ---------------- kernel 1: transpose x -> xT --------------------------------
__global__ void k_transpose(const float* __restrict__ x) {
    int bc = blockIdx.x;                 // b*C + c
    const float* src = x + (size_t)bc * L_;
    float* dst = g_xT + (size_t)bc * L_;
    __shared__ float s[L_];
    for (int i = threadIdx.x; i < L_; i += blockDim.x) s[i] = src[i];
    __syncthreads();
    for (int i = threadIdx.x; i < L_; i += blockDim.x) {
        int w = i / Hh, h = i % Hh;
        dst[i] = s[h * Ww + w];
    }
}

// ---------------- kernel 2: projection GEMM -----------------------------------
__global__ void k_proj(const float* __restrict__ x,
                       const float* __restrict__ Wp) {
    int bs = blockIdx.z;            // b*2 + s
    int b  = bs >> 1, s = bs & 1;
    int p0 = blockIdx.x * 64;

    const float* X = (s ? g_xT : x) + (size_t)b * C_ * L_;

    __shared__ float Ws[16][96];
    __shared__ float Xs[16][64];

    int tid = threadIdx.x;
    int tx = tid & 15, ty = tid >> 4;

    float acc[6][4];
#pragma unroll
    for (int i = 0; i < 6; i++)
#pragma unroll
        for (int j = 0; j < 4; j++) acc[i][j] = 0.f;

    for (int c0 = 0; c0 < C_; c0 += 16) {
        for (int idx = tid; idx < 96 * 16; idx += 256) {
            int m = idx >> 4, kk = idx & 15;
            float v = 0.f;
            if (m < 88) {
                int k = s + (m < D44 ? 0 : 2);
                int d = (m < D44) ? m : (m - D44);
                v = Wp[(size_t)(k * D44 + d) * C_ + c0 + kk];
            }
            Ws[kk][m] = v;
        }
        for (int idx = tid; idx < 16 * 64; idx += 256) {
            int c = idx >> 6, pp = idx & 63;
            Xs[c][pp] = X[(size_t)(c0 + c) * L_ + p0 + pp];
        }
        __syncthreads();
#pragma unroll
        for (int kk = 0; kk < 16; kk++) {
            float xa[4], wa[6];
#pragma unroll
            for (int j = 0; j < 4; j++) xa[j] = Xs[kk][tx + 16 * j];
#pragma unroll
            for (int i = 0; i < 6; i++) wa[i] = Ws[kk][ty + 16 * i];
#pragma unroll
            for (int i = 0; i < 6; i++)
#pragma unroll
                for (int j = 0; j < 4; j++) acc[i][j] = fmaf(wa[i], xa[j], acc[i][j]);
        }
        __syncthreads();
    }

#pragma unroll
    for (int i = 0; i < 6; i++) {
        int m = ty + 16 * i;
        if (m < 88) {
            int k = s + (m < D44 ? 0 : 2);
            int d = (m < D44) ? m : (m - D44);
            float* qrow = g_Q + (size_t)((b * K_ + k) * D44 + d) * L_ + p0;
#pragma unroll
            for (int j = 0; j < 4; j++) qrow[tx + 16 * j] = acc[i][j];
        }
    }
}

// ---------------- kernel 3: dt projection + softplus --------------------------
__global__ void k_dtsp(const float* __restrict__ dtw,
                       const float* __restrict__ dt_bias)
{
    int b = blockIdx.z, k = blockIdx.y;
    int p0 = blockIdx.x * 128;
    __shared__ float dts[R_][128];
    __shared__ float wsm[C_ * R_];

    int tid = threadIdx.x;
    for (int idx = tid; idx < R_ * 128; idx += 256) {
        int r = idx >> 7, pp = idx & 127;
        dts[r][pp] = g_Q[(size_t)((b * K_ + k) * D44 + r) * L_ + p0 + pp];
    }
    for (int idx = tid; idx < C_ * R_; idx += 256)
        wsm[idx] = dtw[(size_t)k * C_ * R_ + idx];
    __syncthreads();

    int pp = tid & 127;
    for (int c = (tid >> 7); c < C_; c += 2) {
        float accv = dt_bias[k * C_ + c];
#pragma unroll
        for (int r = 0; r < R_; r++) accv = fmaf(wsm[c * R_ + r], dts[r][pp], accv);
        float sp = (accv > 20.f) ? accv : log1pf(__expf(accv));
        g_SP[(size_t)((b * K_ + k) * C_ + c) * L_ + p0 + pp] = sp;
    }
}

// ---------------- kernel 4: repack B,C rows, interleaved [p][n][{B,C}] --------
__global__ void k_repack() {
    int b = blockIdx.z, k = blockIdx.y;
    int p0 = blockIdx.x * 64;
    __shared__ float s[32][65];
    int tid = threadIdx.x;
    for (int idx = tid; idx < 32 * 64; idx += 256) {
        int j = idx >> 6, pp = idx & 63;
        s[j][pp] = g_Q[(size_t)((b * K_ + k) * D44 + 12 + j) * L_ + p0 + pp];
    }
    __syncthreads();
    int j = tid & 31;
    int jo = (j < 16) ? (2 * j) : (2 * (j - 16) + 1);
    float* dst = g_BC + ((size_t)(b * K_ + k) * L_ + p0) * 32;
    for (int pp = tid >> 5; pp < 64; pp += 8)
        dst[pp * 32 + jo] = s[j][pp];
}

// ---------------- scan pass 1: chunk-local (h_end, P) -------------------------
template<bool FWD>
__device__ __forceinline__ void scan_p1(
    const float* __restrict__ sp, const float* __restrict__ u,
    const float* __restrict__ bc, float a, int n, int g0,
    float& h, float& P)
{
    h = 0.f; P = 1.f;
    for (int g = g0; g < g0 + GPC; g++) {
        int q = FWD ? 16 * g : (L_ - 16 - 16 * g);
        float spArr[16], uArr[16];
#pragma unroll
        for (int t = 0; t < 4; t++) {
            float4 s4 = *reinterpret_cast<const float4*>(sp + q + 4 * t);
            float4 u4 = *reinterpret_cast<const float4*>(u  + q + 4 * t);
            spArr[4*t+0]=s4.x; spArr[4*t+1]=s4.y; spArr[4*t+2]=s4.z; spArr[4*t+3]=s4.w;
            uArr [4*t+0]=u4.x; uArr [4*t+1]=u4.y; uArr [4*t+2]=u4.z; uArr [4*t+3]=u4.w;
        }
        float Bv[16];
#pragma unroll
        for (int j = 0; j < 16; j++) {
            int mj = FWD ? j : 15 - j;
            Bv[j] = __ldg(bc + (size_t)(q + mj) * 32 + 2 * n);
        }
        float dA[16], dBu[16];
#pragma unroll
        for (int j = 0; j < 16; j++) {
            int mj = FWD ? j : 15 - j;
            float s_ = spArr[mj];
            dA[j]  = __expf(s_ * a);
            dBu[j] = s_ * uArr[mj] * Bv[j];
        }
#pragma unroll
        for (int j = 0; j < 16; j++) {
            h = fmaf(dA[j], h, dBu[j]);
            P = P * dA[j];
        }
    }
}

__global__ __launch_bounds__(128) void k_scan1(
    const float* __restrict__ x, const float* __restrict__ A_logs)
{
    int warpId = threadIdx.x >> 5;
    int lane = threadIdx.x & 31;
    int gw = blockIdx.x * 4 + warpId;       // 0..767
    int s = blockIdx.y;                      // chunk (scan-time)
    int half = lane >> 4, n = lane & 15;
    int ch = gw * 2 + half;                  // 0..1535
    int c = ch % C_;
    int k = (ch / C_) & 3;
    int b = ch / (K_ * C_);
    int kc = k * C_ + c;

    float a = -__expf(A_logs[kc * N_ + n]);

    const float* sp = g_SP + (size_t)ch * L_;
    const float* u  = ((k & 1) ? g_xT : x) + (size_t)(b * C_ + c) * L_;
    const float* bc = g_BC + (size_t)(b * K_ + k) * L_ * 32;

    float h, P;
    if (k < 2) scan_p1<true >(sp, u, bc, a, n, s * GPC, h, P);
    else       scan_p1<false>(sp, u, bc, a, n, s * GPC, h, P);

    size_t o = ((size_t)ch * NCHUNK + s) * N_ + n;
    g_HP[o] = h;
    g_PP[o] = P;
}

// ---------------- combine: serial prefix over chunks --------------------------
__global__ void k_comb() {
    int idx = blockIdx.x * 256 + threadIdx.x;     // ch*16 + n
    if (idx >= KC * B_ * N_) return;
    int ch = idx >> 4, n = idx & 15;
    float h = 0.f;
#pragma unroll
    for (int s = 0; s < NCHUNK; s++) {
        size_t o = ((size_t)ch * NCHUNK + s) * N_ + n;
        float P  = g_PP[o];
        float he = g_HP[o];
        g_HIN[o] = h;
        h = fmaf(P, h, he);
    }
}

// ---------------- scan pass 2: full scan with corrected h0 --------------------
template<bool FWD>
__device__ __forceinline__ void scan_p2(
    const float* __restrict__ sp, const float* __restrict__ u,
    const float* __restrict__ bc, float* __restrict__ y,
    float a, float Dv, int n, int g0, float h)
{
    const unsigned FULL = 0xffffffffu;
    const bool hi8 = (n & 8), hi4 = (n & 4), hi2 = (n & 2), hi1 = (n & 1);

    for (int g = g0; g < g0 + GPC; g++) {
        int q = FWD ? 16 * g : (L_ - 16 - 16 * g);

        float spArr[16], uArr[16];
#pragma unroll
        for (int t = 0; t < 4; t++) {
            float4 s4 = *reinterpret_cast<const float4*>(sp + q + 4 * t);
            float4 u4 = *reinterpret_cast<const float4*>(u  + q + 4 * t);
            spArr[4*t+0]=s4.x; spArr[4*t+1]=s4.y; spArr[4*t+2]=s4.z; spArr[4*t+3]=s4.w;
            uArr [4*t+0]=u4.x; uArr [4*t+1]=u4.y; uArr [4*t+2]=u4.z; uArr [4*t+3]=u4.w;
        }
        float Bv[16], Cv[16];
#pragma unroll
        for (int j = 0; j < 16; j++) {
            int mj = FWD ? j : 15 - j;
            float2 bcv = __ldg(reinterpret_cast<const float2*>(bc + (size_t)(q + mj) * 32) + n);
            Bv[j] = bcv.x; Cv[j] = bcv.y;
        }

        float dA[16], dBu[16];
#pragma unroll
        for (int j = 0; j < 16; j++) {
            int mj = FWD ? j : 15 - j;
            float s_ = spArr[mj];
            dA[j]  = __expf(s_ * a);
            dBu[j] = s_ * uArr[mj] * Bv[j];
        }

        float yp[16];
#pragma unroll
        for (int j = 0; j < 16; j++) {
            h = fmaf(dA[j], h, dBu[j]);
            yp[j] = h * Cv[j];
        }

        float w8[8];
#pragma unroll
        for (int t = 0; t < 8; t++) {
            float keepv = hi8 ? yp[t + 8] : yp[t];
            float sendv = hi8 ? yp[t] : yp[t + 8];
            w8[t] = keepv + __shfl_xor_sync(FULL, sendv, 8);
        }
        float w4[4];
#pragma unroll
        for (int t = 0; t < 4; t++) {
            float keepv = hi4 ? w8[t + 4] : w8[t];
            float sendv = hi4 ? w8[t] : w8[t + 4];
            w4[t] = keepv + __shfl_xor_sync(FULL, sendv, 4);
        }
        float w2[2];
#pragma unroll
        for (int t = 0; t < 2; t++) {
            float keepv = hi2 ? w4[t + 2] : w4[t];
            float sendv = hi2 ? w4[t] : w4[t + 2];
            w2[t] = keepv + __shfl_xor_sync(FULL, sendv, 2);
        }
        {
            float keepv = hi1 ? w2[1] : w2[0];
            float sendv = hi1 ? w2[0] : w2[1];
            float yred = keepv + __shfl_xor_sync(FULL, sendv, 1);
            int p = q + (FWD ? n : 15 - n);
            y[p] = fmaf(Dv, u[p], yred);
        }
    }
}

__global__ __launch_bounds__(128) void k_scan2(
    const float* __restrict__ x,
    const float* __restrict__ A_logs,
    const float* __restrict__ Ds)
{
    int warpId = threadIdx.x >> 5;
    int lane = threadIdx.x & 31;
    int gw = blockIdx.x * 4 + warpId;       // 0..767
    int s = blockIdx.y;                      // chunk (scan-time)
    int half = lane >> 4, n = lane & 15;
    int ch = gw * 2 + half;                  // 0..1535
    int c = ch % C_;
    int k = (ch / C_) & 3;
    int b = ch / (K_ * C_);
    int kc = k * C_ + c;

    float a  = -__expf(A_logs[kc * N_ + n]);
    float Dv = Ds[kc];

    const float* sp = g_SP + (size_t)ch * L_;
    const float* u  = ((k & 1) ? g_xT : x) + (size_t)(b * C_ + c) * L_;
    const float* bc = g_BC + (size_t)(b * K_ + k) * L_ * 32;
    float* y        = g_Y + (size_t)ch * L_;

    float h0 = g_HIN[((size_t)ch * NCHUNK + s) * N_ + n];

    if (k < 2) scan_p2<true >(sp, u, bc, y, a, Dv, n, s * GPC, h0);
    else       scan_p2<false>(sp, u, bc, y, a, Dv, n, s * GPC, h0);
}

// ---------------- kernel 6: cross merge ---------------------------------------
__global__ void k_merge(float* __restrict__ out) {
    int bc = blockIdx.x;
    int b = bc / C_, c = bc % C_;
    const float* y0 = g_Y + (size_t)((b * K_ + 0) * C_ + c) * L_;
    const float* y1 = g_Y + (size_t)((b * K_ + 1) * C_ + c) * L_;
    const float* y2 = g_Y + (size_t)((b * K_ + 2) * C_ + c) * L_;
    const float* y3 = g_Y + (size_t)((b * K_ + 3) * C_ + c) * L_;
    __shared__ float s1[L_];
    for (int i = threadIdx.x; i < L_; i += blockDim.x)
        s1[i] = y1[i] + y3[i];
    __syncthreads();
    float* o = out + (size_t)bc * L_;
    for (int i = threadIdx.x; i < L_; i += blockDim.x) {
        int h = i / Ww, w = i % Ww;
        o[i] = y0[i] + y2[i] + s1[w * Hh + h];
    }
}

// ---------------- launch -------------------------------------------------------
extern "C" void kernel_launch(void* const* d_in, const int* in_sizes, int n_in,
                              void* d_out, int out_size) {
    const float* x       = (const float*)d_in[0];
    const float* xpw     = (const float*)d_in[1];
    const float* dtw     = (const float*)d_in[2];
    const float* A_logs  = (const float*)d_in[3];
    const float* Ds      = (const float*)d_in[4];
    const float* dt_bias = (const float*)d_in[5];
    float* out = (float*)d_out;

    k_transpose<<<B_ * C_, 256>>>(x);

    {
        dim3 grid(L_ / 64, 1, 4);
        k_proj<<<grid, 256>>>(x, xpw);
    }
    {
        dim3 grid(L_ / 128, K_, B_);
        k_dtsp<<<grid, 256>>>(dtw, dt_bias);
    }
    {
        dim3 grid(L_ / 64, K_, B_);
        k_repack<<<grid, 256>>>();
    }
    {
        dim3 grid(192, NCHUNK);
        k_scan1<<<grid, 128>>>(x, A_logs);
    }
    k_comb<<<(KC * B_ * N_ + 255) / 256, 256>>>();
    {
        dim3 grid(192, NCHUNK);
        k_scan2<<<grid, 128>>>(x, A_logs, Ds);
    }
    k_merge<<<B_ * C_, 256>>>(out);
}